// round 6
// baseline (speedup 1.0000x reference)
#include <cuda_runtime.h>
#include <cuda_bf16.h>

// Problem constants
#define Bc 2
#define Fc 512
#define Hc 192
#define Wc 192
#define Tc 8

// Tile: 32 wide x 4 tall = 128 pixels, 4 threads per pixel, 512 threads/block
#define TW 32
#define TH 4
#define NTX (Wc / TW)   // 6
#define NTY (Hc / TH)   // 48
#define NTHREADS 512

__device__ __forceinline__ float ndc_x(int wx) {
    return (2.0f * ((float)wx + 0.5f) - (float)Wc) / (float)Wc;
}
__device__ __forceinline__ float ndc_y(int hy) {
    return (2.0f * ((float)hy + 0.5f) - (float)Hc) / (float)Hc;
}

// Output layout (float32, concatenated in reference return order):
//   feature: (B, 9, H, W) | fim: (B, H, W) as float | dmap: (B, H, W)
#define FEAT_OFF 0
#define FIM_OFF  (Bc * 9 * Hc * Wc)
#define DMAP_OFF (FIM_OFF + Bc * Hc * Wc)

__global__ __launch_bounds__(NTHREADS, 2)
void rasterize_kernel(const float* __restrict__ faces,
                      const float* __restrict__ tex,
                      float* __restrict__ out)
{
    // Raw staged face data (coalesced load), then packed culled faces.
    __shared__ float  sraw[Fc * 9];          // 18 KB
    __shared__ float4 sq0[Fc], sq1[Fc], sq2[Fc];   // 24 KB
    __shared__ int    scount;
    // Merged per-pixel results (handoff to epilogue threads)
    __shared__ float sInv[TW * TH];
    __shared__ int   sF[TW * TH];
    __shared__ float sW0[TW * TH], sW1[TW * TH], sW2[TW * TH];

    const int tid = threadIdx.x;
    const int bid = blockIdx.x;
    const int b   = bid / (NTX * NTY);
    const int t   = bid % (NTX * NTY);
    const int ty  = t / NTX;
    const int tx  = t % NTX;

    const int p  = tid >> 2;       // pixel within tile: 0..127
    const int h  = tid & 3;        // face-list quarter
    const int wx = tx * TW + (p & (TW - 1));
    const int hy = ty * TH + (p >> 5);

    if (tid == 0) scount = 0;

    // Stage face data: 9 fully-coalesced rounds (1 cache line per warp per LDG)
    const float* fb = faces + (size_t)b * Fc * 9;
    #pragma unroll
    for (int i = 0; i < 9; i++) {
        sraw[tid + i * NTHREADS] = fb[tid + i * NTHREADS];
    }
    __syncthreads();

    // Tile NDC bounds (pixel centers)
    const float tpx0 = ndc_x(tx * TW);
    const float tpx1 = ndc_x(tx * TW + TW - 1);
    const float tpy0 = ndc_y(ty * TH);
    const float tpy1 = ndc_y(ty * TH + TH - 1);

    // Cull: exactly one face per thread, read from smem (stride 9 -> conflict-free)
    {
        const float* fp = sraw + tid * 9;
        float x0 = fp[0], y0 = fp[1], z0 = fp[2];
        float x1 = fp[3], y1 = fp[4], z1 = fp[5];
        float x2 = fp[6], y2 = fp[7], z2 = fp[8];

        float det = (x1 - x0) * (y2 - y0) - (x2 - x0) * (y1 - y0);

        float xmn = fminf(x0, fminf(x1, x2));
        float xmx = fmaxf(x0, fmaxf(x1, x2));
        float ymn = fminf(y0, fminf(y1, y2));
        float ymx = fmaxf(y0, fmaxf(y1, y2));

        if (fabsf(det) > 1e-8f &&
            xmx >= tpx0 && xmn <= tpx1 && ymx >= tpy0 && ymn <= tpy1) {
            int pslot = atomicAdd(&scount, 1);
            sq0[pslot] = make_float4(x0, y0, x1, y1);
            sq1[pslot] = make_float4(x2, y2, 1.0f / det, __int_as_float(tid));
            sq2[pslot] = make_float4(1.0f / z0, 1.0f / z1, 1.0f / z2, 0.0f);
        }
    }
    __syncthreads();

    const int n = scount;
    const float px = ndc_x(wx);
    const float py = ndc_y(hy);

    // Track max inverse-depth (monotone equivalent of min depth):
    //   depth < bestD        <=> invd > bestInv
    //   depth >= NEAR (0.5)  <=> invd <= 2.0
    //   depth <  FAR  (100)  <=> invd > 0.01 (depth==FAR never covered)
    float bestInv = 0.01f;
    int   bestF   = -1;
    float bw0 = 0.0f, bw1 = 0.0f, bw2 = 0.0f;

    // Each of the 4 threads of a pixel scans every 4th face.
    #pragma unroll 4
    for (int i = h; i < n; i += 4) {
        float4 q0 = sq0[i];
        float4 q1 = sq1[i];
        float4 q2 = sq2[i];

        float w0 = ((q0.z - px) * (q1.y - py) - (q1.x - px) * (q0.w - py)) * q1.z;
        float w1 = ((q1.x - px) * (q0.y - py) - (q0.x - px) * (q1.y - py)) * q1.z;
        float w2 = 1.0f - w0 - w1;

        float invd = w0 * q2.x + w1 * q2.y + w2 * q2.z;

        bool hit = (w0 >= 0.0f) & (w1 >= 0.0f) & (w2 >= 0.0f)
                 & (invd > bestInv) & (invd <= 2.0f);

        bestInv = hit ? invd : bestInv;
        bestF   = hit ? __float_as_int(q1.w) : bestF;
        bw0     = hit ? w0 : bw0;
        bw1     = hit ? w1 : bw1;
        bw2     = hit ? w2 : bw2;
    }

    // Merge the 4 partial results (lanes 4k..4k+3 of one warp).
    {
        const unsigned m = 0xFFFFFFFFu;
        #pragma unroll
        for (int s = 1; s <= 2; s <<= 1) {
            float oInv = __shfl_xor_sync(m, bestInv, s);
            int   oF   = __shfl_xor_sync(m, bestF,   s);
            float o0   = __shfl_xor_sync(m, bw0,     s);
            float o1   = __shfl_xor_sync(m, bw1,     s);
            float o2   = __shfl_xor_sync(m, bw2,     s);
            bool take = oInv > bestInv;
            bestInv = take ? oInv : bestInv;
            bestF   = take ? oF   : bestF;
            bw0     = take ? o0   : bw0;
            bw1     = take ? o1   : bw1;
            bw2     = take ? o2   : bw2;
        }
    }

    if (h == 0) {
        sInv[p] = bestInv;
        sF[p]   = bestF;
        sW0[p]  = bw0;
        sW1[p]  = bw1;
        sW2[p]  = bw2;
    }
    __syncthreads();

    // Epilogue: threads 0..127 each own one pixel; warp = 32 consecutive wx
    // -> fully coalesced 128B stores per plane.
    if (tid < TW * TH) {
        const int q   = tid;
        const int qwx = tx * TW + (q & (TW - 1));
        const int qhy = ty * TH + (q >> 5);

        float eInv = sInv[q];
        int   eF   = sF[q];
        float e0 = sW0[q], e1 = sW1[q], e2 = sW2[q];

        const bool covered = (eF >= 0);
        const float eD = covered ? (1.0f / eInv) : 100.0f;

        float feat[Tc];
        float mask;
        if (covered) {
            const float4* tp = (const float4*)(tex + (size_t)(b * Fc + eF) * 3 * Tc);
            float4 a0 = tp[0], a1 = tp[1];
            float4 b0 = tp[2], b1 = tp[3];
            float4 c0 = tp[4], c1 = tp[5];
            feat[0] = e0 * a0.x + e1 * b0.x + e2 * c0.x;
            feat[1] = e0 * a0.y + e1 * b0.y + e2 * c0.y;
            feat[2] = e0 * a0.z + e1 * b0.z + e2 * c0.z;
            feat[3] = e0 * a0.w + e1 * b0.w + e2 * c0.w;
            feat[4] = e0 * a1.x + e1 * b1.x + e2 * c1.x;
            feat[5] = e0 * a1.y + e1 * b1.y + e2 * c1.y;
            feat[6] = e0 * a1.z + e1 * b1.z + e2 * c1.z;
            feat[7] = e0 * a1.w + e1 * b1.w + e2 * c1.w;
            mask = 1.0f;
        } else {
            #pragma unroll
            for (int c = 0; c < Tc; c++) feat[c] = 0.0f;
            mask = 0.0f;
        }

        const int pix = (b * Hc + qhy) * Wc + qwx;
        #pragma unroll
        for (int c = 0; c < Tc; c++) {
            out[FEAT_OFF + ((size_t)(b * 9 + c) * Hc + qhy) * Wc + qwx] = feat[c];
        }
        out[FEAT_OFF + ((size_t)(b * 9 + 8) * Hc + qhy) * Wc + qwx] = mask;
        out[FIM_OFF  + (size_t)pix] = (float)eF;
        out[DMAP_OFF + (size_t)pix] = eD;
    }
}

extern "C" void kernel_launch(void* const* d_in, const int* in_sizes, int n_in,
                              void* d_out, int out_size) {
    const float* faces = (const float*)d_in[0];   // (B, F, 3, 3) float32
    const float* tex   = (const float*)d_in[1];   // (B, F, 3, T) float32
    float* out = (float*)d_out;

    dim3 block(NTHREADS);
    dim3 grid(Bc * NTX * NTY);   // 576 tiles
    rasterize_kernel<<<grid, block>>>(faces, tex, out);
}